// round 1
// baseline (speedup 1.0000x reference)
#include <cuda_runtime.h>
#include <cstdint>

// Problem constants (fixed shapes)
#define NB    4
#define NSEQ  512
#define DIMK  64      // dim
#define NCH   256     // attn hidden
#define TJ    128     // j-tile
#define NT    512     // threads per main block

// -------------------- device scratch (no allocations allowed) --------------------
__device__ float d_M   [DIMK * NCH];          // pos_w2 @ attn_w1          [64,256]
__device__ float d_Wq  [DIMK * NCH];          // wqkv_q @ attn_w1          [64,256]
__device__ float d_Wk  [DIMK * NCH];          // wqkv_k @ attn_w1          [64,256]
__device__ float d_cvec[NCH];                 // attn_b1 + pos_b2 @ attn_w1
__device__ float d_qk1 [NB * NSEQ * NCH];     // x @ Wq + cvec             [2048,256]
__device__ float d_kk1 [NB * NSEQ * NCH];     // x @ Wk                    [2048,256]
__device__ float d_v   [NB * NSEQ * DIMK];    // x @ wqkv_v                [2048,64]

// -------------------- packed f32x2 helpers --------------------
__device__ __forceinline__ unsigned long long splat2(float v) {
    unsigned long long r;
    unsigned u = __float_as_uint(v);
    asm("mov.b64 %0, {%1, %1};" : "=l"(r) : "r"(u));
    return r;
}
__device__ __forceinline__ void fma2(unsigned long long& d, unsigned long long a, unsigned long long b) {
    asm("fma.rn.f32x2 %0, %1, %2, %3;" : "=l"(d) : "l"(a), "l"(b), "l"(d));
}
__device__ __forceinline__ float2 unpack2(unsigned long long v) {
    unsigned lo, hi;
    asm("mov.b64 {%0, %1}, %2;" : "=r"(lo), "=r"(hi) : "l"(v));
    float2 r; r.x = __uint_as_float(lo); r.y = __uint_as_float(hi);
    return r;
}

// -------------------- K0a: fold small weight matrices --------------------
// grid 193 x 256. bid<192: (mat = bid/64, row k = bid%64). bid==192: cvec.
__global__ void prep_mats(const float* __restrict__ w_qkv,
                          const float* __restrict__ pos_w2,
                          const float* __restrict__ pos_b2,
                          const float* __restrict__ attn_w1,
                          const float* __restrict__ attn_b1) {
    int c = threadIdx.x;
    int bid = blockIdx.x;
    if (bid == 192) {
        float acc = attn_b1[c];
        #pragma unroll 8
        for (int d = 0; d < DIMK; d++) acc = fmaf(pos_b2[d], attn_w1[d * NCH + c], acc);
        d_cvec[c] = acc;
        return;
    }
    int m = bid >> 6, k = bid & 63;
    const float* src = (m == 0) ? (pos_w2 + k * 64)
                     : (m == 1) ? (w_qkv + k * 192)
                                : (w_qkv + k * 192 + 64);
    float acc = 0.f;
    #pragma unroll 8
    for (int d = 0; d < DIMK; d++) acc = fmaf(src[d], attn_w1[d * NCH + c], acc);
    float* dst = (m == 0) ? d_M : (m == 1) ? d_Wq : d_Wk;
    dst[k * NCH + c] = acc;
}

// -------------------- K0b: per-row projections qk1', kk1, v --------------------
// grid 128 x 256; each block handles 16 rows of the flattened [2048,64] x.
__global__ __launch_bounds__(256) void proj_kernel(const float* __restrict__ x,
                                                   const float* __restrict__ w_qkv) {
    __shared__ float xs[16][64];
    int c = threadIdx.x;
    int row0 = blockIdx.x * 16;
    for (int idx = c; idx < 16 * 64; idx += 256) xs[idx >> 6][idx & 63] = x[row0 * 64 + idx];
    __syncthreads();

    float accq[16], acck[16];
    #pragma unroll
    for (int r = 0; r < 16; r++) { accq[r] = 0.f; acck[r] = 0.f; }
    for (int k = 0; k < 64; k++) {
        float wq = d_Wq[k * NCH + c];
        float wk = d_Wk[k * NCH + c];
        #pragma unroll
        for (int r = 0; r < 16; r++) {
            float xv = xs[r][k];
            accq[r] = fmaf(xv, wq, accq[r]);
            acck[r] = fmaf(xv, wk, acck[r]);
        }
    }
    float cv = d_cvec[c];
    #pragma unroll
    for (int r = 0; r < 16; r++) {
        d_qk1[(size_t)(row0 + r) * NCH + c] = accq[r] + cv;
        d_kk1[(size_t)(row0 + r) * NCH + c] = acck[r];
    }
    // v projection: 256 threads = 4 row-groups x 64 dims
    int d = c & 63, rg = c >> 6;
    for (int r = rg; r < 16; r += 4) {
        float acc = 0.f;
        #pragma unroll 8
        for (int k = 0; k < 64; k++) acc = fmaf(xs[r][k], w_qkv[k * 192 + 128 + d], acc);
        d_v[(size_t)(row0 + r) * 64 + d] = acc;
    }
}

// -------------------- K1: fused per-row attention --------------------
// grid 2048 (one block per (b,i)), 512 threads, ~135.5 KB dynamic smem.
__global__ __launch_bounds__(NT, 1) void pt_main(const float* __restrict__ pos,
                                                 const float* __restrict__ pos_w1,
                                                 const float* __restrict__ pos_b1,
                                                 const float* __restrict__ pos_w2,
                                                 const float* __restrict__ pos_b2,
                                                 const float* __restrict__ attn_w2,
                                                 float* __restrict__ out) {
    extern __shared__ float sm[];
    float* Ms   = sm;             // 16384   M [64][256]
    float* ps   = Ms + 16384;     // 8320    p tile [128][65] (padded)
    float* vs   = ps + 8320;      // 8192    v tile [128][64]
    float* qs   = vs + 8192;      // 256     qk1'(i,:)
    float* w2s  = qs + 256;       // 256     attn_w2
    float* w1s  = w2s + 256;      // 192     pos_w1 [3][64]
    float* b1s  = w1s + 192;      // 64
    float* pj   = b1s + 64;       // 384     pos_j [3][128]
    float* sims = pj + 384;       // 512
    float* gs   = sims + 512;     // 64
    float* red  = gs + 64;        // 64

    int tid = threadIdx.x;
    int bi  = blockIdx.x;         // b*512 + i
    int b   = bi >> 9;

    // stage block-invariant data
    {
        const float4* src = (const float4*)d_M;
        float4* dst = (float4*)Ms;
        for (int idx = tid; idx < 4096; idx += NT) dst[idx] = src[idx];
    }
    if (tid < 256)      { qs[tid] = d_qk1[(size_t)bi * NCH + tid]; w2s[tid] = attn_w2[tid]; }
    else if (tid < 448) { w1s[tid - 256] = pos_w1[tid - 256]; }
    else                { b1s[tid - 448] = pos_b1[tid - 448]; }
    float px = pos[bi * 3 + 0], py = pos[bi * 3 + 1], pz = pos[bi * 3 + 2];
    __syncthreads();

    int jg = tid >> 4;            // 0..31 : j-group (4 rows each)
    int cg = tid & 15;            // 0..15 : channel group
    int jb = jg << 2;

    // ---------------- PASS 1: sims ----------------
    for (int tile = 0; tile < 4; tile++) {
        int j0 = tile * TJ;
        if (tid < 384) {
            int j = tid & 127, d = tid >> 7;
            pj[d * 128 + j] = pos[((size_t)b * NSEQ + j0 + j) * 3 + d];
        }
        __syncthreads();
        // p tile: relu(rel_pos @ pos_w1 + b1)
        for (int idx = tid; idx < TJ * 64; idx += NT) {
            int j = idx >> 6, k = idx & 63;
            float rx = px - pj[j], ry = py - pj[128 + j], rz = pz - pj[256 + j];
            float v = fmaf(rx, w1s[k], fmaf(ry, w1s[64 + k], fmaf(rz, w1s[128 + k], b1s[k])));
            ps[j * 65 + k] = fmaxf(v, 0.f);
        }
        __syncthreads();

        // GEMM: u[128x256] = p @ M, microtile 4j x 16c (8 f32x2 pairs, stride-32)
        unsigned long long acc[4][8];
        #pragma unroll
        for (int jj = 0; jj < 4; jj++)
            #pragma unroll
            for (int t = 0; t < 8; t++) acc[jj][t] = 0ull;

        const float* psr = ps + jb * 65;
        const float* mc  = Ms + (cg << 1);
        #pragma unroll 4
        for (int k = 0; k < 64; k++) {
            unsigned long long p2[4];
            #pragma unroll
            for (int jj = 0; jj < 4; jj++) p2[jj] = splat2(psr[jj * 65 + k]);
            const unsigned long long* mrow = (const unsigned long long*)(mc + k * NCH);
            #pragma unroll
            for (int t = 0; t < 8; t++) {
                unsigned long long mv = mrow[t * 16]; // float offset 32*t
                #pragma unroll
                for (int jj = 0; jj < 4; jj++) fma2(acc[jj][t], p2[jj], mv);
            }
        }

        // epilogue: u = acc + qk1'_i - kk1_j ; relu ; dot w2
        const float* kk = d_kk1 + ((size_t)(b * NSEQ + j0 + jb)) * NCH;
        #pragma unroll
        for (int jj = 0; jj < 4; jj++) {
            float s = 0.f;
            #pragma unroll
            for (int t = 0; t < 8; t++) {
                int c = (cg << 1) + (t << 5);
                float2 kv = *(const float2*)(kk + jj * NCH + c);
                float2 qv = *(const float2*)(qs + c);
                float2 wv = *(const float2*)(w2s + c);
                float2 a  = unpack2(acc[jj][t]);
                float u0 = fmaxf(a.x + qv.x - kv.x, 0.f);
                float u1 = fmaxf(a.y + qv.y - kv.y, 0.f);
                s = fmaf(u0, wv.x, fmaf(u1, wv.y, s));
            }
            s += __shfl_down_sync(0xffffffffu, s, 8, 16);
            s += __shfl_down_sync(0xffffffffu, s, 4, 16);
            s += __shfl_down_sync(0xffffffffu, s, 2, 16);
            s += __shfl_down_sync(0xffffffffu, s, 1, 16);
            if (cg == 0) sims[j0 + jb + jj] = s;
        }
        __syncthreads();
    }

    // ---------------- softmax over 512 sims ----------------
    {
        float s = sims[tid];
        float m = s;
        #pragma unroll
        for (int off = 16; off; off >>= 1) m = fmaxf(m, __shfl_xor_sync(0xffffffffu, m, off));
        if ((tid & 31) == 0) red[tid >> 5] = m;
        __syncthreads();
        if (tid < 32) {
            float v = (tid < 16) ? red[tid] : -3.4e38f;
            #pragma unroll
            for (int off = 8; off; off >>= 1) v = fmaxf(v, __shfl_xor_sync(0xffffffffu, v, off));
            if (tid == 0) red[32] = v;
        }
        __syncthreads();
        float e = __expf(s - red[32]);
        float t = e;
        #pragma unroll
        for (int off = 16; off; off >>= 1) t += __shfl_xor_sync(0xffffffffu, t, off);
        if ((tid & 31) == 0) red[tid >> 5] = t;
        __syncthreads();
        if (tid < 32) {
            float v = (tid < 16) ? red[tid] : 0.f;
            #pragma unroll
            for (int off = 8; off; off >>= 1) v += __shfl_xor_sync(0xffffffffu, v, off);
            if (tid == 0) red[33] = v;
        }
        __syncthreads();
        sims[tid] = e / red[33];
        __syncthreads();
    }

    // ---------------- PASS 2: g = a@p (recompute p), r = a@v ----------------
    float gacc = 0.f, racc = 0.f;
    for (int tile = 0; tile < 4; tile++) {
        int j0 = tile * TJ;
        if (tid < 384) {
            int j = tid & 127, d = tid >> 7;
            pj[d * 128 + j] = pos[((size_t)b * NSEQ + j0 + j) * 3 + d];
        }
        __syncthreads();
        for (int idx = tid; idx < TJ * 64; idx += NT) {
            int j = idx >> 6, k = idx & 63;
            float rx = px - pj[j], ry = py - pj[128 + j], rz = pz - pj[256 + j];
            float v = fmaf(rx, w1s[k], fmaf(ry, w1s[64 + k], fmaf(rz, w1s[128 + k], b1s[k])));
            ps[j * 65 + k] = fmaxf(v, 0.f);
        }
        {
            const float4* src = (const float4*)(d_v + ((size_t)(b * NSEQ + j0)) * 64);
            float4* dst = (float4*)vs;
            for (int idx = tid; idx < TJ * 16; idx += NT) dst[idx] = src[idx];
        }
        __syncthreads();
        if (tid < 64) {
            int k = tid;
            #pragma unroll 8
            for (int j = 0; j < TJ; j++) gacc = fmaf(sims[j0 + j], ps[j * 65 + k], gacc);
        } else if (tid < 128) {
            int d = tid - 64;
            #pragma unroll 8
            for (int j = 0; j < TJ; j++) racc = fmaf(sims[j0 + j], vs[j * 64 + d], racc);
        }
        __syncthreads();
    }

    if (tid < 64) gs[tid] = gacc;
    __syncthreads();
    if (tid >= 64 && tid < 128) {
        int d = tid - 64;
        float o = racc + pos_b2[d];
        #pragma unroll 8
        for (int k = 0; k < 64; k++) o = fmaf(gs[k], pos_w2[k * 64 + d], o);
        out[(size_t)bi * 64 + d] = o;
    }
}

// -------------------- launch --------------------
static const int SMEM_BYTES = 34688 * 4; // 138752

extern "C" void kernel_launch(void* const* d_in, const int* in_sizes, int n_in,
                              void* d_out, int out_size) {
    const float* x       = (const float*)d_in[0];
    const float* pos     = (const float*)d_in[1];
    const float* w_qkv   = (const float*)d_in[2];
    const float* pos_w1  = (const float*)d_in[3];
    const float* pos_b1  = (const float*)d_in[4];
    const float* pos_w2  = (const float*)d_in[5];
    const float* pos_b2  = (const float*)d_in[6];
    const float* attn_w1 = (const float*)d_in[7];
    const float* attn_b1 = (const float*)d_in[8];
    const float* attn_w2 = (const float*)d_in[9];
    // d_in[10] = attn_b2: constant over j -> cancels in softmax, and only enters sim. Unused.
    float* out = (float*)d_out;

    cudaFuncSetAttribute(pt_main, cudaFuncAttributeMaxDynamicSharedMemorySize, SMEM_BYTES);

    prep_mats<<<193, 256>>>(w_qkv, pos_w2, pos_b2, attn_w1, attn_b1);
    proj_kernel<<<128, 256>>>(x, w_qkv);
    pt_main<<<NB * NSEQ, NT, SMEM_BYTES>>>(pos, pos_w1, pos_b1, pos_w2, pos_b2, attn_w2, out);
}